// round 7
// baseline (speedup 1.0000x reference)
#include <cuda_runtime.h>
#include <cuda_bf16.h>
#include <cstdint>

// CombPool2d: out = (w_avg^2)*avg_pool2x2(x) + (w_max^2)*max_pool2x2(x)
// x: (16, 192, 224, 224) fp32 ; w_avg, w_max: (1,192,1,1) ; out: (16,192,112,112)
//
// Pure HBM-streaming kernel. Each thread computes 2 adjacent output pixels:
// reads float4 from input rows 2h' and 2h'+1 (8 floats = two 2x2 windows),
// writes one float2. Fully coalesced 16B-aligned accesses.

#define C_DIM      192
#define H_IN       224
#define W_IN       224
#define H_OUT      112
#define W_OUT      112
#define PAIRS_W    (W_OUT / 2)            // 56 float2 outputs per row
#define PAIRS_PLANE (H_OUT * PAIRS_W)     // 6272 pairs per (b,c) plane
#define THREADS    256

__global__ __launch_bounds__(THREADS)
void combpool2d_kernel(const float* __restrict__ x,
                       const float* __restrict__ w_avg,
                       const float* __restrict__ w_max,
                       float* __restrict__ out)
{
    const int t = blockIdx.x * THREADS + threadIdx.x;   // pair index within plane
    if (t >= PAIRS_PLANE) return;

    const int bc = blockIdx.y;                          // 0 .. B*C-1 (3072)
    const int c  = bc % C_DIM;

    const int hp = t / PAIRS_W;                         // output row 0..111
    const int wp = t % PAIRS_W;                         // float4 column 0..55

    // Input base for this plane and the two source rows (16B-aligned:
    // row stride = 224 floats = 896 B = 56 * 16 B).
    const size_t in_plane = (size_t)bc * (H_IN * W_IN);
    const float4* row0 = reinterpret_cast<const float4*>(x + in_plane + (size_t)(2 * hp)     * W_IN) + wp;
    const float4* row1 = reinterpret_cast<const float4*>(x + in_plane + (size_t)(2 * hp + 1) * W_IN) + wp;

    // Two independent 128-bit loads (MLP=2).
    const float4 a = __ldg(row0);
    const float4 b = __ldg(row1);

    float ca = __ldg(w_avg + c); ca *= ca;
    float cm = __ldg(w_max + c); cm *= cm;

    // Output pixel 0: window {a.x, a.y, b.x, b.y}
    const float avg0 = (a.x + a.y + b.x + b.y) * 0.25f;
    const float mx0  = fmaxf(fmaxf(a.x, a.y), fmaxf(b.x, b.y));
    // Output pixel 1: window {a.z, a.w, b.z, b.w}
    const float avg1 = (a.z + a.w + b.z + b.w) * 0.25f;
    const float mx1  = fmaxf(fmaxf(a.z, a.w), fmaxf(b.z, b.w));

    float2 o;
    o.x = fmaf(ca, avg0, cm * mx0);
    o.y = fmaf(ca, avg1, cm * mx1);

    const size_t out_plane = (size_t)bc * (H_OUT * W_OUT);
    reinterpret_cast<float2*>(out + out_plane + (size_t)hp * W_OUT)[wp] = o;
}

extern "C" void kernel_launch(void* const* d_in, const int* in_sizes, int n_in,
                              void* d_out, int out_size)
{
    const float* x     = (const float*)d_in[0];
    const float* w_avg = (const float*)d_in[1];
    const float* w_max = (const float*)d_in[2];
    float* out = (float*)d_out;

    // B*C planes = total input elements / (H_IN*W_IN)
    const int num_planes = in_sizes[0] / (H_IN * W_IN);   // 16*192 = 3072

    dim3 grid((PAIRS_PLANE + THREADS - 1) / THREADS, num_planes);
    combpool2d_kernel<<<grid, THREADS>>>(x, w_avg, w_max, out);
}

// round 10
// speedup vs baseline: 1.0161x; 1.0161x over previous
#include <cuda_runtime.h>
#include <cuda_bf16.h>
#include <cstdint>

// CombPool2d: out = (w_avg^2)*avg_pool2x2(x) + (w_max^2)*max_pool2x2(x)
// x: (16, 192, 224, 224) fp32 ; w_avg, w_max: (1,192,1,1) ; out: (16,192,112,112)
//
// HBM-streaming kernel, 4 output pixels per thread:
//   reads 2x float4 from input row 2h' and 2x float4 from row 2h'+1 (MLP=4),
//   writes one float4. All accesses 16B-aligned and fully coalesced.
//   __ldcs/__stcs: read-once / write-once streaming, don't retain in L2.

#define C_DIM       192
#define H_IN        224
#define W_IN        224
#define H_OUT       112
#define W_OUT       112
#define QUADS_W     (W_OUT / 4)            // 28 float4 outputs per row
#define QUADS_PLANE (H_OUT * QUADS_W)      // 3136 quads per (b,c) plane
#define THREADS     256

__global__ __launch_bounds__(THREADS)
void combpool2d_kernel(const float* __restrict__ x,
                       const float* __restrict__ w_avg,
                       const float* __restrict__ w_max,
                       float* __restrict__ out)
{
    const int t = blockIdx.x * THREADS + threadIdx.x;   // quad index within plane
    if (t >= QUADS_PLANE) return;

    const int bc = blockIdx.y;                          // 0 .. B*C-1 (3072)
    const int c  = bc % C_DIM;

    const int hp = t / QUADS_W;                         // output row 0..111
    const int wq = t % QUADS_W;                         // float4 column 0..27

    // Input rows 2hp and 2hp+1; row stride 224 floats = 896 B (16B-aligned).
    const size_t in_plane = (size_t)bc * (H_IN * W_IN);
    const float4* r0 = reinterpret_cast<const float4*>(x + in_plane + (size_t)(2 * hp)     * W_IN) + 2 * wq;
    const float4* r1 = reinterpret_cast<const float4*>(x + in_plane + (size_t)(2 * hp + 1) * W_IN) + 2 * wq;

    // Four independent 128-bit streaming loads (front-batched, MLP=4).
    const float4 a0 = __ldcs(r0);
    const float4 a1 = __ldcs(r0 + 1);
    const float4 b0 = __ldcs(r1);
    const float4 b1 = __ldcs(r1 + 1);

    float ca = __ldg(w_avg + c); ca *= ca;
    float cm = __ldg(w_max + c); cm *= cm;

    // 4 output pixels from windows:
    //  {a0.x,a0.y,b0.x,b0.y}, {a0.z,a0.w,b0.z,b0.w},
    //  {a1.x,a1.y,b1.x,b1.y}, {a1.z,a1.w,b1.z,b1.w}
    const float avg0 = (a0.x + a0.y + b0.x + b0.y) * 0.25f;
    const float mx0  = fmaxf(fmaxf(a0.x, a0.y), fmaxf(b0.x, b0.y));
    const float avg1 = (a0.z + a0.w + b0.z + b0.w) * 0.25f;
    const float mx1  = fmaxf(fmaxf(a0.z, a0.w), fmaxf(b0.z, b0.w));
    const float avg2 = (a1.x + a1.y + b1.x + b1.y) * 0.25f;
    const float mx2  = fmaxf(fmaxf(a1.x, a1.y), fmaxf(b1.x, b1.y));
    const float avg3 = (a1.z + a1.w + b1.z + b1.w) * 0.25f;
    const float mx3  = fmaxf(fmaxf(a1.z, a1.w), fmaxf(b1.z, b1.w));

    float4 o;
    o.x = fmaf(ca, avg0, cm * mx0);
    o.y = fmaf(ca, avg1, cm * mx1);
    o.z = fmaf(ca, avg2, cm * mx2);
    o.w = fmaf(ca, avg3, cm * mx3);

    const size_t out_plane = (size_t)bc * (H_OUT * W_OUT);
    __stcs(reinterpret_cast<float4*>(out + out_plane + (size_t)hp * W_OUT) + wq, o);
}

extern "C" void kernel_launch(void* const* d_in, const int* in_sizes, int n_in,
                              void* d_out, int out_size)
{
    const float* x     = (const float*)d_in[0];
    const float* w_avg = (const float*)d_in[1];
    const float* w_max = (const float*)d_in[2];
    float* out = (float*)d_out;

    const int num_planes = in_sizes[0] / (H_IN * W_IN);   // 16*192 = 3072

    dim3 grid((QUADS_PLANE + THREADS - 1) / THREADS, num_planes);
    combpool2d_kernel<<<grid, THREADS>>>(x, w_avg, w_max, out);
}